// round 13
// baseline (speedup 1.0000x reference)
#include <cuda_runtime.h>
#include <cuda_bf16.h>
#include <mma.h>
#include <math.h>
#include <stdint.h>

using namespace nvcuda;

#define B_ 256
#define Q_ 128
#define P_ 16
#define D_ 256
#define H_ 16
#define F_ 512
#define DK_ 16
#define MROWS (B_*Q_)        // 32768
#define SCALE_ 0.25f         // DK^-0.5
#define EPS_ 1e-5f

// ---- scratch (device globals: allocation-free) ----
__device__ float g_z [MROWS*D_];
__device__ float g_q [MROWS*D_];
__device__ float g_k [MROWS*D_];
__device__ float g_v [MROWS*D_];
__device__ float g_o [MROWS*D_];
__device__ float g_t [MROWS*D_];
__device__ float g_f [MROWS*F_];
__device__ float g_sc[(size_t)B_*H_*Q_*Q_];   // 268 MB score carry

// ================= split-bf16 WMMA GEMM =================
// C[M,N] = act(A[M,K] @ W[K,N] + bias)
// 128x128 tile, BK=32, 256 threads (8 warps, 2x4), 64x32 per warp.
// D += Ah*Bh + Ah*Bl + Al*Bh  (Dekker split, lo*lo dropped)

#define LDA 40    // bf16 elems per A smem row (32 + 8 pad)
#define LDB 136   // bf16 elems per B smem row (128 + 8 pad)
#define LDC 132   // f32 elems per C staging row
#define SM_AH 0
#define SM_AL 10240            // 128*40*2
#define SM_BH 20480
#define SM_BL 29184            // +32*136*2
#define SM_GEMM_BYTES (128*LDC*4)   // 67584 staging tile dominates

template<int ACT>
__global__ __launch_bounds__(256, 1)
void gemm_tc(const float* __restrict__ A,
             const float* __restrict__ W,
             const float* __restrict__ bias,
             float* __restrict__ C,
             int N, int K) {
    extern __shared__ char smem[];
    __nv_bfloat16* Ah = (__nv_bfloat16*)(smem + SM_AH);
    __nv_bfloat16* Al = (__nv_bfloat16*)(smem + SM_AL);
    __nv_bfloat16* Bh = (__nv_bfloat16*)(smem + SM_BH);
    __nv_bfloat16* Bl = (__nv_bfloat16*)(smem + SM_BL);
    float* Cs = (float*)smem;
    __shared__ float bias_s[128];

    const int tid  = threadIdx.x;
    const int wid  = tid >> 5;
    const int warpM = wid >> 2;       // 0..1
    const int warpN = wid & 3;        // 0..3
    const int m0 = blockIdx.y * 128, n0 = blockIdx.x * 128;

    if (tid < 128) bias_s[tid] = bias[n0 + tid];

    wmma::fragment<wmma::accumulator, 16, 16, 16, float> acc[4][2];
#pragma unroll
    for (int i = 0; i < 4; ++i)
#pragma unroll
        for (int j = 0; j < 2; ++j) wmma::fill_fragment(acc[i][j], 0.0f);

    const int aRow0 = tid >> 3, aK4 = (tid & 7) << 2;     // A: 32 rows x 32 cols per pass
    const int bK0   = tid >> 5, bN4 = (tid & 31) << 2;    // B: 8 k-rows x 128 cols per pass

    const int nChunks = K >> 5;
    for (int c = 0; c < nChunks; ++c) {
        const int kc = c << 5;
        __syncthreads();
        // ---- load + split A chunk [128 x 32] ----
#pragma unroll
        for (int it = 0; it < 4; ++it) {
            const int row = aRow0 + it * 32;
            float4 a4 = *(const float4*)&A[(size_t)(m0 + row) * K + kc + aK4];
            float f[4] = {a4.x, a4.y, a4.z, a4.w};
            __nv_bfloat16 h[4], l[4];
#pragma unroll
            for (int p = 0; p < 4; ++p) {
                h[p] = __float2bfloat16(f[p]);
                l[p] = __float2bfloat16(f[p] - __bfloat162float(h[p]));
            }
            *(uint2*)&Ah[row*LDA + aK4] = *(uint2*)h;
            *(uint2*)&Al[row*LDA + aK4] = *(uint2*)l;
        }
        // ---- load + split B chunk [32 x 128] ----
#pragma unroll
        for (int it = 0; it < 4; ++it) {
            const int kr = bK0 + it * 8;    // 0..31
            float4 b4 = *(const float4*)&W[(size_t)(kc + kr) * N + n0 + bN4];
            float f[4] = {b4.x, b4.y, b4.z, b4.w};
            __nv_bfloat16 h[4], l[4];
#pragma unroll
            for (int p = 0; p < 4; ++p) {
                h[p] = __float2bfloat16(f[p]);
                l[p] = __float2bfloat16(f[p] - __bfloat162float(h[p]));
            }
            *(uint2*)&Bh[kr*LDB + bN4] = *(uint2*)h;
            *(uint2*)&Bl[kr*LDB + bN4] = *(uint2*)l;
        }
        __syncthreads();

        // ---- 2 k-steps of 16 ----
#pragma unroll
        for (int ks = 0; ks < 2; ++ks) {
            wmma::fragment<wmma::matrix_a, 16,16,16, __nv_bfloat16, wmma::row_major> fa_h[4], fa_l[4];
            wmma::fragment<wmma::matrix_b, 16,16,16, __nv_bfloat16, wmma::row_major> fb_h[2], fb_l[2];
#pragma unroll
            for (int i = 0; i < 4; ++i) {
                const __nv_bfloat16* ap = Ah + (warpM*64 + i*16)*LDA + ks*16;
                wmma::load_matrix_sync(fa_h[i], ap, LDA);
                wmma::load_matrix_sync(fa_l[i], ap + (SM_AL - SM_AH)/2, LDA);
            }
#pragma unroll
            for (int j = 0; j < 2; ++j) {
                const __nv_bfloat16* bp = Bh + (ks*16)*LDB + warpN*32 + j*16;
                wmma::load_matrix_sync(fb_h[j], bp, LDB);
                wmma::load_matrix_sync(fb_l[j], bp + (SM_BL - SM_BH)/2, LDB);
            }
#pragma unroll
            for (int i = 0; i < 4; ++i)
#pragma unroll
                for (int j = 0; j < 2; ++j) {
                    wmma::mma_sync(acc[i][j], fa_h[i], fb_h[j], acc[i][j]);
                    wmma::mma_sync(acc[i][j], fa_h[i], fb_l[j], acc[i][j]);
                    wmma::mma_sync(acc[i][j], fa_l[i], fb_h[j], acc[i][j]);
                }
        }
    }

    // ---- epilogue: stage to smem, add bias (+GELU), write coalesced ----
    __syncthreads();
#pragma unroll
    for (int i = 0; i < 4; ++i)
#pragma unroll
        for (int j = 0; j < 2; ++j)
            wmma::store_matrix_sync(&Cs[(warpM*64 + i*16)*LDC + warpN*32 + j*16],
                                    acc[i][j], LDC, wmma::mem_row_major);
    __syncthreads();

    for (int idx = tid; idx < 128*32; idx += 256) {
        const int row = idx >> 5, c4 = (idx & 31) << 2;
        float r[4];
#pragma unroll
        for (int p = 0; p < 4; ++p) {
            float v = Cs[row*LDC + c4 + p] + bias_s[c4 + p];
            if (ACT == 1) v = 0.5f*v*(1.0f + erff(v*0.70710678118654752f));
            r[p] = v;
        }
        *(float4*)&C[(size_t)(m0 + row)*N + n0 + c4] = *(float4*)r;
    }
}

// ---------------- embed: z = x @ W_P + b_P + W_pos ----------------
__global__ void embed_kernel(const float* __restrict__ x,
                             const float* __restrict__ W_P,
                             const float* __restrict__ b_P,
                             const float* __restrict__ W_pos) {
    int row = blockIdx.x;          // b*Q + q
    int d   = threadIdx.x;         // 0..255
    int q   = row % Q_;
    __shared__ float xs[P_];
    if (threadIdx.x < P_) xs[threadIdx.x] = x[row*P_ + threadIdx.x];
    __syncthreads();
    float acc = b_P[d] + W_pos[q*D_ + d];
#pragma unroll
    for (int p = 0; p < P_; ++p) acc += xs[p] * W_P[p*D_ + d];
    g_z[(size_t)row*D_ + d] = acc;
}

// ---------------- fused attention per (b,h), coalesced score IO ----------------
__global__ void attn_kernel(const float* __restrict__ q,
                            const float* __restrict__ k,
                            const float* __restrict__ v,
                            const float* __restrict__ bias,
                            float* __restrict__ scores,
                            float* __restrict__ o,
                            int hasPrev, int writeScores) {
    const int h = blockIdx.x, b = blockIdx.y;
    const int tid = threadIdx.x;                  // 128 threads = query rows
    extern __shared__ float sm[];
    float* ks = sm;                               // 128*16
    float* vs = sm + Q_*DK_;                      // 128*16
    float* ss = sm + 2*Q_*DK_;                    // 128*(128+1)

    const size_t base  = ((size_t)b*Q_)*D_ + h*DK_;
    const size_t sbase = (((size_t)b*H_ + h)*Q_)*Q_;

    for (int t = tid; t < Q_*DK_; t += 128) {
        int j = t >> 4, c = t & 15;
        ks[t] = k[base + (size_t)j*D_ + c];
        vs[t] = v[base + (size_t)j*D_ + c];
    }
    if (hasPrev) {
        for (int idx = tid; idx < Q_*Q_; idx += 128)
            ss[(idx >> 7)*(Q_+1) + (idx & 127)] = bias[idx] + scores[sbase + idx];
    } else {
        for (int idx = tid; idx < Q_*Q_; idx += 128)
            ss[(idx >> 7)*(Q_+1) + (idx & 127)] = bias[idx];
    }
    float qr[DK_];
#pragma unroll
    for (int c = 0; c < DK_; ++c) qr[c] = q[base + (size_t)tid*D_ + c];
    __syncthreads();

    float* my = ss + tid*(Q_+1);
    float mx = -1e30f;
    for (int j = 0; j < Q_; ++j) {
        float dot = 0.f;
#pragma unroll
        for (int c = 0; c < DK_; ++c) dot += qr[c]*ks[j*DK_ + c];
        float s = dot*SCALE_ + my[j];
        my[j] = s;
        mx = fmaxf(mx, s);
    }

    if (writeScores) {
        __syncthreads();
        for (int idx = tid; idx < Q_*Q_; idx += 128)
            scores[sbase + idx] = ss[(idx >> 7)*(Q_+1) + (idx & 127)];
        __syncthreads();
    }

    float sum = 0.f;
    for (int j = 0; j < Q_; ++j) { float e = __expf(my[j]-mx); my[j] = e; sum += e; }
    const float inv = 1.0f/sum;

    float oa[DK_] = {};
    for (int j = 0; j < Q_; ++j) {
        float p = my[j];
#pragma unroll
        for (int c = 0; c < DK_; ++c) oa[c] += p*vs[j*DK_ + c];
    }
#pragma unroll
    for (int c = 0; c < DK_; ++c) o[base + (size_t)tid*D_ + c] = oa[c]*inv;
}

// ---------------- fused residual + LayerNorm ----------------
__global__ void ln_kernel(const float* __restrict__ resid,
                          const float* __restrict__ add,
                          const float* __restrict__ g,
                          const float* __restrict__ bta,
                          float* __restrict__ out) {
    const int row = blockIdx.x, d = threadIdx.x;  // 256 threads
    __shared__ float w1s[8], w2s[8];
    float val = resid[(size_t)row*D_ + d] + add[(size_t)row*D_ + d];
    float s1 = val, s2 = val*val;
#pragma unroll
    for (int o = 16; o; o >>= 1) {
        s1 += __shfl_xor_sync(0xffffffffu, s1, o);
        s2 += __shfl_xor_sync(0xffffffffu, s2, o);
    }
    if ((d & 31) == 0) { w1s[d >> 5] = s1; w2s[d >> 5] = s2; }
    __syncthreads();
    float t1 = 0.f, t2 = 0.f;
#pragma unroll
    for (int i = 0; i < 8; ++i) { t1 += w1s[i]; t2 += w2s[i]; }
    float mu  = t1 * (1.0f/256.0f);
    float var = t2 * (1.0f/256.0f) - mu*mu;
    out[(size_t)row*D_ + d] = (val - mu) * rsqrtf(var + EPS_) * g[d] + bta[d];
}

// ---------------- launch ----------------
extern "C" void kernel_launch(void* const* d_in, const int* in_sizes, int n_in,
                              void* d_out, int out_size) {
    const float* x    = (const float*)d_in[0];
    const float* bias = (const float*)d_in[1];
    const float* W_P  = (const float*)d_in[2];
    const float* b_P  = (const float*)d_in[3];
    const float* Wpos = (const float*)d_in[4];
    const float* Wq   = (const float*)d_in[5];
    const float* bq   = (const float*)d_in[6];
    const float* Wk   = (const float*)d_in[7];
    const float* bk   = (const float*)d_in[8];
    const float* Wv   = (const float*)d_in[9];
    const float* bv   = (const float*)d_in[10];
    const float* Wo   = (const float*)d_in[11];
    const float* bo   = (const float*)d_in[12];
    const float* g1   = (const float*)d_in[13];
    const float* be1  = (const float*)d_in[14];
    const float* W1   = (const float*)d_in[15];
    const float* b1   = (const float*)d_in[16];
    const float* W2   = (const float*)d_in[17];
    const float* b2   = (const float*)d_in[18];
    const float* g2   = (const float*)d_in[19];
    const float* be2  = (const float*)d_in[20];
    float* out = (float*)d_out;

    float *z,*qb,*kb,*vb,*ob,*tb,*fb,*sc;
    cudaGetSymbolAddress((void**)&z,  g_z);
    cudaGetSymbolAddress((void**)&qb, g_q);
    cudaGetSymbolAddress((void**)&kb, g_k);
    cudaGetSymbolAddress((void**)&vb, g_v);
    cudaGetSymbolAddress((void**)&ob, g_o);
    cudaGetSymbolAddress((void**)&tb, g_t);
    cudaGetSymbolAddress((void**)&fb, g_f);
    cudaGetSymbolAddress((void**)&sc, g_sc);

    const int attnSmem = (2*Q_*DK_ + Q_*(Q_+1)) * (int)sizeof(float);  // 82432
    cudaFuncSetAttribute(attn_kernel, cudaFuncAttributeMaxDynamicSharedMemorySize, attnSmem);
    cudaFuncSetAttribute(gemm_tc<0>, cudaFuncAttributeMaxDynamicSharedMemorySize, SM_GEMM_BYTES);
    cudaFuncSetAttribute(gemm_tc<1>, cudaFuncAttributeMaxDynamicSharedMemorySize, SM_GEMM_BYTES);

    embed_kernel<<<MROWS, 256>>>(x, W_P, b_P, Wpos);

    dim3 gD(D_/128, MROWS/128);   // (2, 256)
    dim3 gF(F_/128, MROWS/128);   // (4, 256)

    for (int l = 0; l < 3; ++l) {
        const float* wq = Wq + (size_t)l*D_*D_;  const float* bq_ = bq + (size_t)l*D_;
        const float* wk = Wk + (size_t)l*D_*D_;  const float* bk_ = bk + (size_t)l*D_;
        const float* wv = Wv + (size_t)l*D_*D_;  const float* bv_ = bv + (size_t)l*D_;
        const float* wo = Wo + (size_t)l*D_*D_;  const float* bo_ = bo + (size_t)l*D_;
        const float* w1 = W1 + (size_t)l*D_*F_;  const float* b1_ = b1 + (size_t)l*F_;
        const float* w2 = W2 + (size_t)l*F_*D_;  const float* b2_ = b2 + (size_t)l*D_;
        const float* g1_ = g1 + (size_t)l*D_;    const float* be1_ = be1 + (size_t)l*D_;
        const float* g2_ = g2 + (size_t)l*D_;    const float* be2_ = be2 + (size_t)l*D_;

        gemm_tc<0><<<gD, 256, SM_GEMM_BYTES>>>(z, wq, bq_, qb, D_, D_);
        gemm_tc<0><<<gD, 256, SM_GEMM_BYTES>>>(z, wk, bk_, kb, D_, D_);
        gemm_tc<0><<<gD, 256, SM_GEMM_BYTES>>>(z, wv, bv_, vb, D_, D_);

        attn_kernel<<<dim3(H_, B_), 128, attnSmem>>>(qb, kb, vb, bias, sc, ob,
                                                     (l > 0) ? 1 : 0, (l < 2) ? 1 : 0);

        gemm_tc<0><<<gD, 256, SM_GEMM_BYTES>>>(ob, wo, bo_, tb, D_, D_);
        ln_kernel<<<MROWS, 256>>>(z, tb, g1_, be1_, z);

        gemm_tc<1><<<gF, 256, SM_GEMM_BYTES>>>(z, w1, b1_, fb, F_, D_);
        gemm_tc<0><<<gD, 256, SM_GEMM_BYTES>>>(fb, w2, b2_, tb, D_, F_);
        ln_kernel<<<MROWS, 256>>>(z, tb, g2_, be2_, (l == 2) ? out : z);
    }
}

// round 14
// speedup vs baseline: 1.4795x; 1.4795x over previous
#include <cuda_runtime.h>
#include <cuda_bf16.h>
#include <mma.h>
#include <math.h>
#include <stdint.h>

using namespace nvcuda;

#define B_ 256
#define Q_ 128
#define P_ 16
#define D_ 256
#define H_ 16
#define F_ 512
#define DK_ 16
#define MROWS (B_*Q_)        // 32768
#define SCALE_ 0.25f         // DK^-0.5
#define EPS_ 1e-5f

// ---- scratch (device globals: allocation-free) ----
__device__ float g_z [MROWS*D_];
__device__ float g_q [MROWS*D_];
__device__ float g_k [MROWS*D_];
__device__ float g_v [MROWS*D_];
__device__ float g_o [MROWS*D_];
__device__ float g_t [MROWS*D_];
__device__ float g_f [MROWS*F_];
__device__ float g_sc[(size_t)B_*H_*Q_*Q_];   // 268 MB score carry
// split-precision buffers
__device__ __nv_bfloat16 g_ah[MROWS*F_];      // activation hi (max size M x F)
__device__ __nv_bfloat16 g_al[MROWS*F_];      // activation lo
#define WSTRIDE 524288                         // per-layer weight elements
__device__ __nv_bfloat16 g_wh[3*WSTRIDE];
__device__ __nv_bfloat16 g_wl[3*WSTRIDE];
// per-layer weight offsets: WQ 0, WK 65536, WV 131072, WO 196608, W1 262144, W2 393216

// ================= split kernels =================
__global__ void split_act(const float* __restrict__ in,
                          __nv_bfloat16* __restrict__ hi,
                          __nv_bfloat16* __restrict__ lo, int n4) {
    int i = blockIdx.x * 256 + threadIdx.x;
    if (i >= n4) return;
    float4 f4 = *(const float4*)(in + (size_t)i * 4);
    float f[4] = {f4.x, f4.y, f4.z, f4.w};
    __nv_bfloat16 h[4], l[4];
#pragma unroll
    for (int p = 0; p < 4; ++p) {
        h[p] = __float2bfloat16(f[p]);
        l[p] = __float2bfloat16(f[p] - __bfloat162float(h[p]));
    }
    *(uint2*)(hi + (size_t)i * 4) = *(uint2*)h;
    *(uint2*)(lo + (size_t)i * 4) = *(uint2*)l;
}

// split all 6 weights of one layer. grid=(128, 6)
__global__ void split_w6(const float* __restrict__ w0, const float* __restrict__ w1,
                         const float* __restrict__ w2, const float* __restrict__ w3,
                         const float* __restrict__ w4, const float* __restrict__ w5,
                         __nv_bfloat16* __restrict__ hi, __nv_bfloat16* __restrict__ lo) {
    const int sel = blockIdx.y;
    const float* src; int off, n;
    switch (sel) {
        case 0: src = w0; off = 0;      n = 65536;  break;
        case 1: src = w1; off = 65536;  n = 65536;  break;
        case 2: src = w2; off = 131072; n = 65536;  break;
        case 3: src = w3; off = 196608; n = 65536;  break;
        case 4: src = w4; off = 262144; n = 131072; break;
        default:src = w5; off = 393216; n = 131072; break;
    }
    int i = blockIdx.x * 256 + threadIdx.x;       // float4 index
    if (i * 4 >= n) return;
    float4 f4 = *(const float4*)(src + (size_t)i * 4);
    float f[4] = {f4.x, f4.y, f4.z, f4.w};
    __nv_bfloat16 h[4], l[4];
#pragma unroll
    for (int p = 0; p < 4; ++p) {
        h[p] = __float2bfloat16(f[p]);
        l[p] = __float2bfloat16(f[p] - __bfloat162float(h[p]));
    }
    *(uint2*)(hi + off + (size_t)i * 4) = *(uint2*)h;
    *(uint2*)(lo + off + (size_t)i * 4) = *(uint2*)l;
}

// ================= split-bf16 WMMA GEMM, cp.async double-buffered =================
// C[M,N] = act(A[M,K] @ W[K,N] + bias);  D += Ah*Bh + Ah*Bl + Al*Bh
// 128x128 tile, BK=32, 256 threads (8 warps 2x4), 64x32 per warp.

#define LDA 40    // bf16 per A smem row (32 + 8 pad); 80 B
#define LDB 136   // bf16 per B smem row (128 + 8 pad); 272 B
#define LDC 132
#define SA_H 0
#define SA_L 10240
#define SB_H 20480
#define SB_L 29184
#define STAGE 37888
#define SM_GEMM_BYTES (2*STAGE)    // 75776 >= 128*LDC*4=67584 epilogue staging

__device__ __forceinline__ void cp16(uint32_t saddr, const void* gaddr) {
    asm volatile("cp.async.cg.shared.global [%0], [%1], 16;" :: "r"(saddr), "l"(gaddr));
}

template<int ACT>
__global__ __launch_bounds__(256)
void gemm_bf(const __nv_bfloat16* __restrict__ Ahp, const __nv_bfloat16* __restrict__ Alp,
             const __nv_bfloat16* __restrict__ Whp, const __nv_bfloat16* __restrict__ Wlp,
             const float* __restrict__ bias, float* __restrict__ C,
             int N, int K) {
    extern __shared__ char smem[];
    float* Cs = (float*)smem;
    __shared__ float bias_s[128];

    const uint32_t sb = (uint32_t)__cvta_generic_to_shared(smem);
    const int tid  = threadIdx.x;
    const int wid  = tid >> 5;
    const int warpM = wid >> 2;
    const int warpN = wid & 3;
    const int m0 = blockIdx.y * 128, n0 = blockIdx.x * 128;

    if (tid < 128) bias_s[tid] = bias[n0 + tid];

    // cp.async lane mappings
    const int aRow = tid >> 1, aSeg = (tid & 1) << 1;    // A: 2x 16B segs -> 2 it covers 4 segs
    const int bRow = tid >> 3, bSeg = (tid & 7) << 1;    // B: rows 0..31, 16 segs of 16B

    wmma::fragment<wmma::accumulator, 16, 16, 16, float> acc[4][2];
#pragma unroll
    for (int i = 0; i < 4; ++i)
#pragma unroll
        for (int j = 0; j < 2; ++j) wmma::fill_fragment(acc[i][j], 0.0f);

    const int nChunks = K >> 5;

    // issue copies for chunk c into stage s
    auto issue = [&](int c, int s) {
        const int kc = c << 5;
        const uint32_t st = sb + s * STAGE;
        // A: 128 rows x 4 segs (16B) ; thread covers (aRow, aSeg..aSeg+1)
#pragma unroll
        for (int t = 0; t < 2; ++t) {
            const int seg = aSeg + t;
            cp16(st + SA_H + aRow*80 + seg*16, Ahp + (size_t)(m0 + aRow)*K + kc + seg*8);
            cp16(st + SA_L + aRow*80 + seg*16, Alp + (size_t)(m0 + aRow)*K + kc + seg*8);
        }
        // B: 32 rows x 16 segs ; thread covers (bRow, bSeg..bSeg+1)
#pragma unroll
        for (int t = 0; t < 2; ++t) {
            const int seg = bSeg + t;
            cp16(st + SB_H + bRow*272 + seg*16, Whp + (size_t)(kc + bRow)*N + n0 + seg*8);
            cp16(st + SB_L + bRow*272 + seg*16, Wlp + (size_t)(kc + bRow)*N + n0 + seg*8);
        }
    };

    issue(0, 0);
    asm volatile("cp.async.commit_group;" ::: "memory");

    for (int c = 0; c < nChunks; ++c) {
        if (c + 1 < nChunks) {
            issue(c + 1, (c + 1) & 1);
            asm volatile("cp.async.commit_group;" ::: "memory");
            asm volatile("cp.async.wait_group 1;" ::: "memory");
        } else {
            asm volatile("cp.async.wait_group 0;" ::: "memory");
        }
        __syncthreads();

        const __nv_bfloat16* Ah = (const __nv_bfloat16*)(smem + (c & 1) * STAGE + SA_H);
        const __nv_bfloat16* Bh = (const __nv_bfloat16*)(smem + (c & 1) * STAGE + SB_H);
#pragma unroll
        for (int ks = 0; ks < 2; ++ks) {
            wmma::fragment<wmma::matrix_a, 16,16,16, __nv_bfloat16, wmma::row_major> fa_h[4], fa_l[4];
            wmma::fragment<wmma::matrix_b, 16,16,16, __nv_bfloat16, wmma::row_major> fb_h[2], fb_l[2];
#pragma unroll
            for (int i = 0; i < 4; ++i) {
                const __nv_bfloat16* ap = Ah + (warpM*64 + i*16)*LDA + ks*16;
                wmma::load_matrix_sync(fa_h[i], ap, LDA);
                wmma::load_matrix_sync(fa_l[i], ap + (SA_L - SA_H)/2, LDA);
            }
#pragma unroll
            for (int j = 0; j < 2; ++j) {
                const __nv_bfloat16* bp = Bh + (ks*16)*LDB + warpN*32 + j*16;
                wmma::load_matrix_sync(fb_h[j], bp, LDB);
                wmma::load_matrix_sync(fb_l[j], bp + (SB_L - SB_H)/2, LDB);
            }
#pragma unroll
            for (int i = 0; i < 4; ++i)
#pragma unroll
                for (int j = 0; j < 2; ++j) {
                    wmma::mma_sync(acc[i][j], fa_h[i], fb_h[j], acc[i][j]);
                    wmma::mma_sync(acc[i][j], fa_h[i], fb_l[j], acc[i][j]);
                    wmma::mma_sync(acc[i][j], fa_l[i], fb_h[j], acc[i][j]);
                }
        }
        __syncthreads();
    }

    // ---- epilogue ----
#pragma unroll
    for (int i = 0; i < 4; ++i)
#pragma unroll
        for (int j = 0; j < 2; ++j)
            wmma::store_matrix_sync(&Cs[(warpM*64 + i*16)*LDC + warpN*32 + j*16],
                                    acc[i][j], LDC, wmma::mem_row_major);
    __syncthreads();

    for (int idx = tid; idx < 128*32; idx += 256) {
        const int row = idx >> 5, c4 = (idx & 31) << 2;
        float r[4];
#pragma unroll
        for (int p = 0; p < 4; ++p) {
            float v = Cs[row*LDC + c4 + p] + bias_s[c4 + p];
            if (ACT == 1) v = 0.5f*v*(1.0f + erff(v*0.70710678118654752f));
            r[p] = v;
        }
        *(float4*)&C[(size_t)(m0 + row)*N + n0 + c4] = *(float4*)r;
    }
}

// ---------------- embed: z = x @ W_P + b_P + W_pos ----------------
__global__ void embed_kernel(const float* __restrict__ x,
                             const float* __restrict__ W_P,
                             const float* __restrict__ b_P,
                             const float* __restrict__ W_pos) {
    int row = blockIdx.x;          // b*Q + q
    int d   = threadIdx.x;         // 0..255
    int q   = row % Q_;
    __shared__ float xs[P_];
    if (threadIdx.x < P_) xs[threadIdx.x] = x[row*P_ + threadIdx.x];
    __syncthreads();
    float acc = b_P[d] + W_pos[q*D_ + d];
#pragma unroll
    for (int p = 0; p < P_; ++p) acc += xs[p] * W_P[p*D_ + d];
    g_z[(size_t)row*D_ + d] = acc;
}

// ---------------- fused attention per (b,h), coalesced score IO ----------------
__global__ void attn_kernel(const float* __restrict__ q,
                            const float* __restrict__ k,
                            const float* __restrict__ v,
                            const float* __restrict__ bias,
                            float* __restrict__ scores,
                            float* __restrict__ o,
                            int hasPrev, int writeScores) {
    const int h = blockIdx.x, b = blockIdx.y;
    const int tid = threadIdx.x;                  // 128 threads = query rows
    extern __shared__ float sm[];
    float* ks = sm;                               // 128*16
    float* vs = sm + Q_*DK_;                      // 128*16
    float* ss = sm + 2*Q_*DK_;                    // 128*(128+1)

    const size_t base  = ((size_t)b*Q_)*D_ + h*DK_;
    const size_t sbase = (((size_t)b*H_ + h)*Q_)*Q_;

    for (int t = tid; t < Q_*DK_; t += 128) {
        int j = t >> 4, c = t & 15;
        ks[t] = k[base + (size_t)j*D_ + c];
        vs[t] = v[base + (size_t)j*D_ + c];
    }
    if (hasPrev) {
        for (int idx = tid; idx < Q_*Q_; idx += 128)
            ss[(idx >> 7)*(Q_+1) + (idx & 127)] = bias[idx] + scores[sbase + idx];
    } else {
        for (int idx = tid; idx < Q_*Q_; idx += 128)
            ss[(idx >> 7)*(Q_+1) + (idx & 127)] = bias[idx];
    }
    float qr[DK_];
#pragma unroll
    for (int c = 0; c < DK_; ++c) qr[c] = q[base + (size_t)tid*D_ + c];
    __syncthreads();

    float* my = ss + tid*(Q_+1);
    float mx = -1e30f;
    for (int j = 0; j < Q_; ++j) {
        float dot = 0.f;
#pragma unroll
        for (int c = 0; c < DK_; ++c) dot += qr[c]*ks[j*DK_ + c];
        float s = dot*SCALE_ + my[j];
        my[j] = s;
        mx = fmaxf(mx, s);
    }

    if (writeScores) {
        __syncthreads();
        for (int idx = tid; idx < Q_*Q_; idx += 128)
            scores[sbase + idx] = ss[(idx >> 7)*(Q_+1) + (idx & 127)];
        __syncthreads();
    }

    float sum = 0.f;
    for (int j = 0; j < Q_; ++j) { float e = __expf(my[j]-mx); my[j] = e; sum += e; }
    const float inv = 1.0f/sum;

    float oa[DK_] = {};
    for (int j = 0; j < Q_; ++j) {
        float p = my[j];
#pragma unroll
        for (int c = 0; c < DK_; ++c) oa[c] += p*vs[j*DK_ + c];
    }
#pragma unroll
    for (int c = 0; c < DK_; ++c) o[base + (size_t)tid*D_ + c] = oa[c]*inv;
}

// ---------------- fused residual + LayerNorm ----------------
__global__ void ln_kernel(const float* __restrict__ resid,
                          const float* __restrict__ add,
                          const float* __restrict__ g,
                          const float* __restrict__ bta,
                          float* __restrict__ out) {
    const int row = blockIdx.x, d = threadIdx.x;  // 256 threads
    __shared__ float w1s[8], w2s[8];
    float val = resid[(size_t)row*D_ + d] + add[(size_t)row*D_ + d];
    float s1 = val, s2 = val*val;
#pragma unroll
    for (int o = 16; o; o >>= 1) {
        s1 += __shfl_xor_sync(0xffffffffu, s1, o);
        s2 += __shfl_xor_sync(0xffffffffu, s2, o);
    }
    if ((d & 31) == 0) { w1s[d >> 5] = s1; w2s[d >> 5] = s2; }
    __syncthreads();
    float t1 = 0.f, t2 = 0.f;
#pragma unroll
    for (int i = 0; i < 8; ++i) { t1 += w1s[i]; t2 += w2s[i]; }
    float mu  = t1 * (1.0f/256.0f);
    float var = t2 * (1.0f/256.0f) - mu*mu;
    out[(size_t)row*D_ + d] = (val - mu) * rsqrtf(var + EPS_) * g[d] + bta[d];
}

// ---------------- launch ----------------
extern "C" void kernel_launch(void* const* d_in, const int* in_sizes, int n_in,
                              void* d_out, int out_size) {
    const float* x    = (const float*)d_in[0];
    const float* bias = (const float*)d_in[1];
    const float* W_P  = (const float*)d_in[2];
    const float* b_P  = (const float*)d_in[3];
    const float* Wpos = (const float*)d_in[4];
    const float* Wq   = (const float*)d_in[5];
    const float* bq   = (const float*)d_in[6];
    const float* Wk   = (const float*)d_in[7];
    const float* bk   = (const float*)d_in[8];
    const float* Wv   = (const float*)d_in[9];
    const float* bv   = (const float*)d_in[10];
    const float* Wo   = (const float*)d_in[11];
    const float* bo   = (const float*)d_in[12];
    const float* g1   = (const float*)d_in[13];
    const float* be1  = (const float*)d_in[14];
    const float* W1   = (const float*)d_in[15];
    const float* b1   = (const float*)d_in[16];
    const float* W2   = (const float*)d_in[17];
    const float* b2   = (const float*)d_in[18];
    const float* g2   = (const float*)d_in[19];
    const float* be2  = (const float*)d_in[20];
    float* out = (float*)d_out;

    float *z,*qb,*kb,*vb,*ob,*tb,*fb,*sc;
    __nv_bfloat16 *ah,*al,*wh,*wl;
    cudaGetSymbolAddress((void**)&z,  g_z);
    cudaGetSymbolAddress((void**)&qb, g_q);
    cudaGetSymbolAddress((void**)&kb, g_k);
    cudaGetSymbolAddress((void**)&vb, g_v);
    cudaGetSymbolAddress((void**)&ob, g_o);
    cudaGetSymbolAddress((void**)&tb, g_t);
    cudaGetSymbolAddress((void**)&fb, g_f);
    cudaGetSymbolAddress((void**)&sc, g_sc);
    cudaGetSymbolAddress((void**)&ah, g_ah);
    cudaGetSymbolAddress((void**)&al, g_al);
    cudaGetSymbolAddress((void**)&wh, g_wh);
    cudaGetSymbolAddress((void**)&wl, g_wl);

    const int attnSmem = (2*Q_*DK_ + Q_*(Q_+1)) * (int)sizeof(float);  // 82432
    cudaFuncSetAttribute(attn_kernel, cudaFuncAttributeMaxDynamicSharedMemorySize, attnSmem);
    cudaFuncSetAttribute(gemm_bf<0>, cudaFuncAttributeMaxDynamicSharedMemorySize, SM_GEMM_BYTES);
    cudaFuncSetAttribute(gemm_bf<1>, cudaFuncAttributeMaxDynamicSharedMemorySize, SM_GEMM_BYTES);

    embed_kernel<<<MROWS, 256>>>(x, W_P, b_P, Wpos);

    // split all weights (once per run; inputs are constant across replays)
    for (int l = 0; l < 3; ++l) {
        split_w6<<<dim3(128, 6), 256>>>(Wq + (size_t)l*D_*D_, Wk + (size_t)l*D_*D_,
                                        Wv + (size_t)l*D_*D_, Wo + (size_t)l*D_*D_,
                                        W1 + (size_t)l*D_*F_, W2 + (size_t)l*F_*D_,
                                        wh + (size_t)l*WSTRIDE, wl + (size_t)l*WSTRIDE);
    }

    dim3 gD(D_/128, MROWS/128);   // (2, 256)
    dim3 gF(F_/128, MROWS/128);   // (4, 256)
    const int nD4 = MROWS*D_/4, nF4 = MROWS*F_/4;

    for (int l = 0; l < 3; ++l) {
        const size_t wo_ = (size_t)l*WSTRIDE;
        const float* bq_ = bq + (size_t)l*D_;
        const float* bk_ = bk + (size_t)l*D_;
        const float* bv_ = bv + (size_t)l*D_;
        const float* bo_ = bo + (size_t)l*D_;
        const float* b1_ = b1 + (size_t)l*F_;
        const float* b2_ = b2 + (size_t)l*D_;
        const float* g1_ = g1 + (size_t)l*D_;    const float* be1_ = be1 + (size_t)l*D_;
        const float* g2_ = g2 + (size_t)l*D_;    const float* be2_ = be2 + (size_t)l*D_;

        split_act<<<(nD4+255)/256, 256>>>(z, ah, al, nD4);
        gemm_bf<0><<<gD, 256, SM_GEMM_BYTES>>>(ah, al, wh+wo_,        wl+wo_,        bq_, qb, D_, D_);
        gemm_bf<0><<<gD, 256, SM_GEMM_BYTES>>>(ah, al, wh+wo_+65536,  wl+wo_+65536,  bk_, kb, D_, D_);
        gemm_bf<0><<<gD, 256, SM_GEMM_BYTES>>>(ah, al, wh+wo_+131072, wl+wo_+131072, bv_, vb, D_, D_);

        attn_kernel<<<dim3(H_, B_), 128, attnSmem>>>(qb, kb, vb, bias, sc, ob,
                                                     (l > 0) ? 1 : 0, (l < 2) ? 1 : 0);

        split_act<<<(nD4+255)/256, 256>>>(ob, ah, al, nD4);
        gemm_bf<0><<<gD, 256, SM_GEMM_BYTES>>>(ah, al, wh+wo_+196608, wl+wo_+196608, bo_, tb, D_, D_);
        ln_kernel<<<MROWS, 256>>>(z, tb, g1_, be1_, z);

        split_act<<<(nD4+255)/256, 256>>>(z, ah, al, nD4);
        gemm_bf<1><<<gF, 256, SM_GEMM_BYTES>>>(ah, al, wh+wo_+262144, wl+wo_+262144, b1_, fb, F_, D_);
        split_act<<<(nF4+255)/256, 256>>>(fb, ah, al, nF4);
        gemm_bf<0><<<gD, 256, SM_GEMM_BYTES>>>(ah, al, wh+wo_+393216, wl+wo_+393216, b2_, tb, D_, F_);
        ln_kernel<<<MROWS, 256>>>(z, tb, g2_, be2_, (l == 2) ? out : z);
    }
}

// round 16
// speedup vs baseline: 1.6714x; 1.1297x over previous
#include <cuda_runtime.h>
#include <cuda_bf16.h>
#include <mma.h>
#include <math.h>
#include <stdint.h>

using namespace nvcuda;

#define B_ 256
#define Q_ 128
#define P_ 16
#define D_ 256
#define H_ 16
#define F_ 512
#define DK_ 16
#define MROWS (B_*Q_)        // 32768
#define SCALE_ 0.25f         // DK^-0.5
#define EPS_ 1e-5f

// ---- scratch (device globals: allocation-free) ----
__device__ float g_z [MROWS*D_];
__device__ float g_q [MROWS*D_];
__device__ float g_k [MROWS*D_];
__device__ float g_v [MROWS*D_];
__device__ float g_t [MROWS*D_];
__device__ float g_sc[(size_t)B_*H_*Q_*Q_];   // 268 MB score carry
// split-precision buffers (activation pair A, pair B)
__device__ __nv_bfloat16 g_ah[MROWS*F_];
__device__ __nv_bfloat16 g_al[MROWS*F_];
__device__ __nv_bfloat16 g_bh[MROWS*F_];
__device__ __nv_bfloat16 g_bl[MROWS*F_];
#define WSTRIDE 524288
__device__ __nv_bfloat16 g_wh[3*WSTRIDE];
__device__ __nv_bfloat16 g_wl[3*WSTRIDE];
// weight offsets within layer: WQ 0, WK 65536, WV 131072, WO 196608, W1 262144, W2 393216

__device__ __forceinline__ void splt(float f, __nv_bfloat16& h, __nv_bfloat16& l) {
    h = __float2bfloat16(f);
    l = __float2bfloat16(f - __bfloat162float(h));
}

// ================= weight split (once per run) =================
__global__ void split_w6(const float* __restrict__ w0, const float* __restrict__ w1,
                         const float* __restrict__ w2, const float* __restrict__ w3,
                         const float* __restrict__ w4, const float* __restrict__ w5,
                         __nv_bfloat16* __restrict__ hi, __nv_bfloat16* __restrict__ lo) {
    const int sel = blockIdx.y;
    const float* src; int off, n;
    switch (sel) {
        case 0: src = w0; off = 0;      n = 65536;  break;
        case 1: src = w1; off = 65536;  n = 65536;  break;
        case 2: src = w2; off = 131072; n = 65536;  break;
        case 3: src = w3; off = 196608; n = 65536;  break;
        case 4: src = w4; off = 262144; n = 131072; break;
        default:src = w5; off = 393216; n = 131072; break;
    }
    int i = blockIdx.x * 256 + threadIdx.x;
    if (i * 4 >= n) return;
    float4 f4 = *(const float4*)(src + (size_t)i * 4);
    float f[4] = {f4.x, f4.y, f4.z, f4.w};
    __nv_bfloat16 h[4], l[4];
#pragma unroll
    for (int p = 0; p < 4; ++p) splt(f[p], h[p], l[p]);
    *(uint2*)(hi + off + (size_t)i * 4) = *(uint2*)h;
    *(uint2*)(lo + off + (size_t)i * 4) = *(uint2*)l;
}

// ================= split-bf16 WMMA GEMM, cp.async double-buffered =================
#define LDA 40
#define LDB 136
#define LDC 132
#define SA_H 0
#define SA_L 10240
#define SB_H 20480
#define SB_L 29184
#define STAGE 37888
#define SM_GEMM_BYTES (2*STAGE)

__device__ __forceinline__ void cp16(uint32_t saddr, const void* gaddr) {
    asm volatile("cp.async.cg.shared.global [%0], [%1], 16;" :: "r"(saddr), "l"(gaddr));
}

// OSPLIT=0: write fp32 C ; OSPLIT=1: write bf16 hi/lo pair (Oh/Ol)
template<int ACT, int OSPLIT>
__global__ __launch_bounds__(256)
void gemm_bf(const __nv_bfloat16* __restrict__ Ahp, const __nv_bfloat16* __restrict__ Alp,
             const __nv_bfloat16* __restrict__ Whp, const __nv_bfloat16* __restrict__ Wlp,
             const float* __restrict__ bias, float* __restrict__ C,
             __nv_bfloat16* __restrict__ Oh, __nv_bfloat16* __restrict__ Ol,
             int N, int K) {
    extern __shared__ char smem[];
    float* Cs = (float*)smem;
    __shared__ float bias_s[128];

    const uint32_t sb = (uint32_t)__cvta_generic_to_shared(smem);
    const int tid  = threadIdx.x;
    const int wid  = tid >> 5;
    const int warpM = wid >> 2;
    const int warpN = wid & 3;
    const int m0 = blockIdx.y * 128, n0 = blockIdx.x * 128;

    if (tid < 128) bias_s[tid] = bias[n0 + tid];

    const int aRow = tid >> 1, aSeg = (tid & 1) << 1;
    const int bRow = tid >> 3, bSeg = (tid & 7) << 1;

    wmma::fragment<wmma::accumulator, 16, 16, 16, float> acc[4][2];
#pragma unroll
    for (int i = 0; i < 4; ++i)
#pragma unroll
        for (int j = 0; j < 2; ++j) wmma::fill_fragment(acc[i][j], 0.0f);

    const int nChunks = K >> 5;

    auto issue = [&](int c, int s) {
        const int kc = c << 5;
        const uint32_t st = sb + s * STAGE;
#pragma unroll
        for (int t = 0; t < 2; ++t) {
            const int seg = aSeg + t;
            cp16(st + SA_H + aRow*80 + seg*16, Ahp + (size_t)(m0 + aRow)*K + kc + seg*8);
            cp16(st + SA_L + aRow*80 + seg*16, Alp + (size_t)(m0 + aRow)*K + kc + seg*8);
        }
#pragma unroll
        for (int t = 0; t < 2; ++t) {
            const int seg = bSeg + t;
            cp16(st + SB_H + bRow*272 + seg*16, Whp + (size_t)(kc + bRow)*N + n0 + seg*8);
            cp16(st + SB_L + bRow*272 + seg*16, Wlp + (size_t)(kc + bRow)*N + n0 + seg*8);
        }
    };

    issue(0, 0);
    asm volatile("cp.async.commit_group;" ::: "memory");

    for (int c = 0; c < nChunks; ++c) {
        if (c + 1 < nChunks) {
            issue(c + 1, (c + 1) & 1);
            asm volatile("cp.async.commit_group;" ::: "memory");
            asm volatile("cp.async.wait_group 1;" ::: "memory");
        } else {
            asm volatile("cp.async.wait_group 0;" ::: "memory");
        }
        __syncthreads();

        const __nv_bfloat16* Ah = (const __nv_bfloat16*)(smem + (c & 1) * STAGE + SA_H);
        const __nv_bfloat16* Bh = (const __nv_bfloat16*)(smem + (c & 1) * STAGE + SB_H);
#pragma unroll
        for (int ks = 0; ks < 2; ++ks) {
            wmma::fragment<wmma::matrix_a, 16,16,16, __nv_bfloat16, wmma::row_major> fa_h[4], fa_l[4];
            wmma::fragment<wmma::matrix_b, 16,16,16, __nv_bfloat16, wmma::row_major> fb_h[2], fb_l[2];
#pragma unroll
            for (int i = 0; i < 4; ++i) {
                const __nv_bfloat16* ap = Ah + (warpM*64 + i*16)*LDA + ks*16;
                wmma::load_matrix_sync(fa_h[i], ap, LDA);
                wmma::load_matrix_sync(fa_l[i], ap + (SA_L - SA_H)/2, LDA);
            }
#pragma unroll
            for (int j = 0; j < 2; ++j) {
                const __nv_bfloat16* bp = Bh + (ks*16)*LDB + warpN*32 + j*16;
                wmma::load_matrix_sync(fb_h[j], bp, LDB);
                wmma::load_matrix_sync(fb_l[j], bp + (SB_L - SB_H)/2, LDB);
            }
#pragma unroll
            for (int i = 0; i < 4; ++i)
#pragma unroll
                for (int j = 0; j < 2; ++j) {
                    wmma::mma_sync(acc[i][j], fa_h[i], fb_h[j], acc[i][j]);
                    wmma::mma_sync(acc[i][j], fa_h[i], fb_l[j], acc[i][j]);
                    wmma::mma_sync(acc[i][j], fa_l[i], fb_h[j], acc[i][j]);
                }
        }
        __syncthreads();
    }

    // ---- epilogue ----
#pragma unroll
    for (int i = 0; i < 4; ++i)
#pragma unroll
        for (int j = 0; j < 2; ++j)
            wmma::store_matrix_sync(&Cs[(warpM*64 + i*16)*LDC + warpN*32 + j*16],
                                    acc[i][j], LDC, wmma::mem_row_major);
    __syncthreads();

    for (int idx = tid; idx < 128*32; idx += 256) {
        const int row = idx >> 5, c4 = (idx & 31) << 2;
        float r[4];
#pragma unroll
        for (int p = 0; p < 4; ++p) {
            float v = Cs[row*LDC + c4 + p] + bias_s[c4 + p];
            if (ACT == 1) v = 0.5f*v*(1.0f + erff(v*0.70710678118654752f));
            r[p] = v;
        }
        if (OSPLIT) {
            __nv_bfloat16 h[4], l[4];
#pragma unroll
            for (int p = 0; p < 4; ++p) splt(r[p], h[p], l[p]);
            *(uint2*)(Oh + (size_t)(m0 + row)*N + n0 + c4) = *(uint2*)h;
            *(uint2*)(Ol + (size_t)(m0 + row)*N + n0 + c4) = *(uint2*)l;
        } else {
            *(float4*)&C[(size_t)(m0 + row)*N + n0 + c4] = *(float4*)r;
        }
    }
}

// ---------------- embed: z = x @ W_P + b_P + W_pos ; emits fp32 + split ----------------
__global__ void embed_kernel(const float* __restrict__ x,
                             const float* __restrict__ W_P,
                             const float* __restrict__ b_P,
                             const float* __restrict__ W_pos,
                             __nv_bfloat16* __restrict__ zh,
                             __nv_bfloat16* __restrict__ zl) {
    int row = blockIdx.x;          // b*Q + q
    int d   = threadIdx.x;         // 0..255
    int q   = row % Q_;
    __shared__ float xs[P_];
    if (threadIdx.x < P_) xs[threadIdx.x] = x[row*P_ + threadIdx.x];
    __syncthreads();
    float acc = b_P[d] + W_pos[q*D_ + d];
#pragma unroll
    for (int p = 0; p < P_; ++p) acc += xs[p] * W_P[p*D_ + d];
    g_z[(size_t)row*D_ + d] = acc;
    __nv_bfloat16 h, l; splt(acc, h, l);
    zh[(size_t)row*D_ + d] = h;
    zl[(size_t)row*D_ + d] = l;
}

// ---------------- fused attention: 64 query rows/CTA, lane-pair j-split ----------------
// grid (H_, B_, 2), block 128.  o emitted pre-split into oh/ol.
__global__ void attn_kernel(const float* __restrict__ q,
                            const float* __restrict__ k,
                            const float* __restrict__ v,
                            const float* __restrict__ bias,
                            float* __restrict__ scores,
                            __nv_bfloat16* __restrict__ oh,
                            __nv_bfloat16* __restrict__ ol,
                            int hasPrev, int writeScores) {
    const int h = blockIdx.x, b = blockIdx.y, rb = blockIdx.z;
    const int tid  = threadIdx.x;          // 128
    const int row  = tid >> 1;             // 0..63 local query row
    const int half = tid & 1;              // j half
    extern __shared__ float sm[];
    float* ks = sm;                        // 128*16
    float* vs = sm + Q_*DK_;               // 128*16
    float* ss = sm + 2*Q_*DK_;             // 64*(128+1)

    const size_t base  = ((size_t)b*Q_)*D_ + h*DK_;
    const int    qrow0 = rb * 64;
    const size_t sbase = (((size_t)b*H_ + h)*Q_ + qrow0)*Q_;

    for (int t = tid; t < Q_*DK_; t += 128) {
        int j = t >> 4, c = t & 15;
        ks[t] = k[base + (size_t)j*D_ + c];
        vs[t] = v[base + (size_t)j*D_ + c];
    }
    const float* brow = bias + (size_t)qrow0*Q_;
    if (hasPrev) {
        for (int idx = tid; idx < 64*Q_; idx += 128)
            ss[(idx >> 7)*(Q_+1) + (idx & 127)] = brow[idx] + scores[sbase + idx];
    } else {
        for (int idx = tid; idx < 64*Q_; idx += 128)
            ss[(idx >> 7)*(Q_+1) + (idx & 127)] = brow[idx];
    }
    float qr[DK_];
#pragma unroll
    for (int c = 0; c < DK_; ++c) qr[c] = q[base + (size_t)(qrow0 + row)*D_ + c];
    __syncthreads();

    float* my = ss + row*(Q_+1);
    const int j0 = half * 64;
    float mx = -1e30f;
#pragma unroll 4
    for (int jj = 0; jj < 64; ++jj) {
        const int j = j0 + jj;
        float dot = 0.f;
#pragma unroll
        for (int c = 0; c < DK_; ++c) dot += qr[c]*ks[j*DK_ + c];
        float s = dot*SCALE_ + my[j];
        my[j] = s;
        mx = fmaxf(mx, s);
    }
    mx = fmaxf(mx, __shfl_xor_sync(0xffffffffu, mx, 1));

    if (writeScores) {
        __syncthreads();
        for (int idx = tid; idx < 64*Q_; idx += 128)
            scores[sbase + idx] = ss[(idx >> 7)*(Q_+1) + (idx & 127)];
        __syncthreads();
    }

    float sum = 0.f;
#pragma unroll 4
    for (int jj = 0; jj < 64; ++jj) {
        float e = __expf(my[j0 + jj] - mx);
        my[j0 + jj] = e;
        sum += e;
    }
    sum += __shfl_xor_sync(0xffffffffu, sum, 1);
    const float inv = 1.0f / sum;

    float oa[DK_] = {};
#pragma unroll 4
    for (int jj = 0; jj < 64; ++jj) {
        const float p = my[j0 + jj];
#pragma unroll
        for (int c = 0; c < DK_; ++c) oa[c] += p*vs[(j0 + jj)*DK_ + c];
    }
#pragma unroll
    for (int c = 0; c < DK_; ++c)
        oa[c] += __shfl_xor_sync(0xffffffffu, oa[c], 1);

    // each pair thread writes 8 of the 16 channels, pre-split (8 bf16 = 16 B = uint4)
    const size_t obase = base + (size_t)(qrow0 + row)*D_ + half*8;
    __nv_bfloat16 hh[8], ll[8];
#pragma unroll
    for (int c = 0; c < 8; ++c) splt(oa[half*8 + c]*inv, hh[c], ll[c]);
    *(uint4*)(oh + obase) = *(uint4*)hh;
    *(uint4*)(ol + obase) = *(uint4*)ll;
}

// ---------------- fused residual + LayerNorm ; emits fp32 + split ----------------
__global__ void ln_kernel(const float* __restrict__ resid,
                          const float* __restrict__ add,
                          const float* __restrict__ g,
                          const float* __restrict__ bta,
                          float* __restrict__ out,
                          __nv_bfloat16* __restrict__ zh,
                          __nv_bfloat16* __restrict__ zl) {
    const int row = blockIdx.x, d = threadIdx.x;  // 256 threads
    __shared__ float w1s[8], w2s[8];
    float val = resid[(size_t)row*D_ + d] + add[(size_t)row*D_ + d];
    float s1 = val, s2 = val*val;
#pragma unroll
    for (int o = 16; o; o >>= 1) {
        s1 += __shfl_xor_sync(0xffffffffu, s1, o);
        s2 += __shfl_xor_sync(0xffffffffu, s2, o);
    }
    if ((d & 31) == 0) { w1s[d >> 5] = s1; w2s[d >> 5] = s2; }
    __syncthreads();
    float t1 = 0.f, t2 = 0.f;
#pragma unroll
    for (int i = 0; i < 8; ++i) { t1 += w1s[i]; t2 += w2s[i]; }
    float mu  = t1 * (1.0f/256.0f);
    float var = t2 * (1.0f/256.0f) - mu*mu;
    float r = (val - mu) * rsqrtf(var + EPS_) * g[d] + bta[d];
    out[(size_t)row*D_ + d] = r;
    __nv_bfloat16 h, l; splt(r, h, l);
    zh[(size_t)row*D_ + d] = h;
    zl[(size_t)row*D_ + d] = l;
}

// ---------------- launch ----------------
extern "C" void kernel_launch(void* const* d_in, const int* in_sizes, int n_in,
                              void* d_out, int out_size) {
    const float* x    = (const float*)d_in[0];
    const float* bias = (const float*)d_in[1];
    const float* W_P  = (const float*)d_in[2];
    const float* b_P  = (const float*)d_in[3];
    const float* Wpos = (const float*)d_in[4];
    const float* Wq   = (const float*)d_in[5];
    const float* bq   = (const float*)d_in[6];
    const float* Wk   = (const float*)d_in[7];
    const float* bk   = (const float*)d_in[8];
    const float* Wv   = (const float*)d_in[9];
    const float* bv   = (const float*)d_in[10];
    const float* Wo   = (const float*)d_in[11];
    const float* bo   = (const float*)d_in[12];
    const float* g1   = (const float*)d_in[13];
    const float* be1  = (const float*)d_in[14];
    const float* W1   = (const float*)d_in[15];
    const float* b1   = (const float*)d_in[16];
    const float* W2   = (const float*)d_in[17];
    const float* b2   = (const float*)d_in[18];
    const float* g2   = (const float*)d_in[19];
    const float* be2  = (const float*)d_in[20];
    float* out = (float*)d_out;

    float *z,*qb,*kb,*vb,*tb,*sc;
    __nv_bfloat16 *ah,*al,*bh2,*bl2,*wh,*wl;
    cudaGetSymbolAddress((void**)&z,  g_z);
    cudaGetSymbolAddress((void**)&qb, g_q);
    cudaGetSymbolAddress((void**)&kb, g_k);
    cudaGetSymbolAddress((void**)&vb, g_v);
    cudaGetSymbolAddress((void**)&tb, g_t);
    cudaGetSymbolAddress((void**)&sc, g_sc);
    cudaGetSymbolAddress((void**)&ah, g_ah);
    cudaGetSymbolAddress((void**)&al, g_al);
    cudaGetSymbolAddress((void**)&bh2, g_bh);
    cudaGetSymbolAddress((void**)&bl2, g_bl);
    cudaGetSymbolAddress((void**)&wh, g_wh);
    cudaGetSymbolAddress((void**)&wl, g_wl);

    const int attnSmem = (2*Q_*DK_ + 64*(Q_+1)) * (int)sizeof(float);   // 49408
    cudaFuncSetAttribute(attn_kernel, cudaFuncAttributeMaxDynamicSharedMemorySize, attnSmem);
    cudaFuncSetAttribute(gemm_bf<0,0>, cudaFuncAttributeMaxDynamicSharedMemorySize, SM_GEMM_BYTES);
    cudaFuncSetAttribute(gemm_bf<1,1>, cudaFuncAttributeMaxDynamicSharedMemorySize, SM_GEMM_BYTES);

    embed_kernel<<<MROWS, 256>>>(x, W_P, b_P, Wpos, ah, al);

    for (int l = 0; l < 3; ++l) {
        split_w6<<<dim3(128, 6), 256>>>(Wq + (size_t)l*D_*D_, Wk + (size_t)l*D_*D_,
                                        Wv + (size_t)l*D_*D_, Wo + (size_t)l*D_*D_,
                                        W1 + (size_t)l*D_*F_, W2 + (size_t)l*F_*D_,
                                        wh + (size_t)l*WSTRIDE, wl + (size_t)l*WSTRIDE);
    }

    dim3 gD(D_/128, MROWS/128);   // (2, 256)
    dim3 gF(F_/128, MROWS/128);   // (4, 256)

    for (int l = 0; l < 3; ++l) {
        const size_t wo_ = (size_t)l*WSTRIDE;
        const float* bq_ = bq + (size_t)l*D_;
        const float* bk_ = bk + (size_t)l*D_;
        const float* bv_ = bv + (size_t)l*D_;
        const float* bo_ = bo + (size_t)l*D_;
        const float* b1_ = b1 + (size_t)l*F_;
        const float* b2_ = b2 + (size_t)l*D_;
        const float* g1_ = g1 + (size_t)l*D_;    const float* be1_ = be1 + (size_t)l*D_;
        const float* g2_ = g2 + (size_t)l*D_;    const float* be2_ = be2 + (size_t)l*D_;

        // QKV from (ah,al) = split(z)
        gemm_bf<0,0><<<gD, 256, SM_GEMM_BYTES>>>(ah, al, wh+wo_,        wl+wo_,        bq_, qb, 0, 0, D_, D_);
        gemm_bf<0,0><<<gD, 256, SM_GEMM_BYTES>>>(ah, al, wh+wo_+65536,  wl+wo_+65536,  bk_, kb, 0, 0, D_, D_);
        gemm_bf<0,0><<<gD, 256, SM_GEMM_BYTES>>>(ah, al, wh+wo_+131072, wl+wo_+131072, bv_, vb, 0, 0, D_, D_);

        // attention writes split(o) into (ah,al) — z-split no longer needed
        attn_kernel<<<dim3(H_, B_, 2), 128, attnSmem>>>(qb, kb, vb, bias, sc, ah, al,
                                                        (l > 0) ? 1 : 0, (l < 2) ? 1 : 0);

        gemm_bf<0,0><<<gD, 256, SM_GEMM_BYTES>>>(ah, al, wh+wo_+196608, wl+wo_+196608, bo_, tb, 0, 0, D_, D_);
        ln_kernel<<<MROWS, 256>>>(z, tb, g1_, be1_, z, ah, al);     // z + split for W1

        // W1 (GELU) writes split directly into (bh2,bl2)
        gemm_bf<1,1><<<gF, 256, SM_GEMM_BYTES>>>(ah, al, wh+wo_+262144, wl+wo_+262144, b1_, 0, bh2, bl2, F_, D_);
        gemm_bf<0,0><<<gD, 256, SM_GEMM_BYTES>>>(bh2, bl2, wh+wo_+393216, wl+wo_+393216, b2_, tb, 0, 0, D_, F_);
        ln_kernel<<<MROWS, 256>>>(z, tb, g2_, be2_, (l == 2) ? out : z, ah, al);  // split feeds next QKV
    }
}